// round 10
// baseline (speedup 1.0000x reference)
#include <cuda_runtime.h>
#include <cuda_pipeline.h>
#include <cuda_fp16.h>
#include <cstdint>

// SJCSNN spiking CNN forward, T=8, B=32, out [32,7] f32.
// conv2 AND fc1: fp16 mma.m16n8k16, scaled 2-term weight split, single fp32 acc
//   (spikes {0,1} exact in fp16; lo-term A = spikes*2^-11 via bit-mask trick,
//    lo-term B = (w - fp16(w)) * 2^11).
// R10: k3 full-plane M tile (576 px), mf=9, triple-buffered cp.async.

#define NTB 256  // T*B

// ---- scratch (device globals; no allocations) ----
__device__ __align__(16) uint32_t g_p1h[NTB * 64 * 676];   // IF1+pool spikes, fp16 pair-packed, PADDED 26x26
__device__ __align__(16) float g_c2[NTB * 128 * 24 * 24];  // conv2+bn2 output
__device__ __align__(16) uint32_t g_fh[NTB * 9216];        // IF2+pool spikes, fp16 pair-packed flat
__device__ float g_y1p[16 * NTB * 1152];                   // fc1 split-K partials (16)
__device__ __align__(16) float g_l1[NTB * 1152];           // LIF1 spikes
__device__ float g_y2[NTB * 128];                          // fc2 output
__device__ float g_l2[NTB * 128];                          // LIF2 spikes
// conv2 weights fp16 split: [tap(9)][cinpair(64)][cout(128)][hi,lo] as half2 words
__device__ __align__(16) uint32_t g_w2p[9 * 64 * 128 * 2];

// ---------------- mma helper ----------------
__device__ __forceinline__ void mma_f16(float c[4], const uint32_t a[4],
                                        uint32_t b0, uint32_t b1) {
    asm volatile(
        "mma.sync.aligned.m16n8k16.row.col.f32.f16.f16.f32 "
        "{%0,%1,%2,%3}, {%4,%5,%6,%7}, {%8,%9}, {%0,%1,%2,%3};"
        : "+f"(c[0]), "+f"(c[1]), "+f"(c[2]), "+f"(c[3])
        : "r"(a[0]), "r"(a[1]), "r"(a[2]), "r"(a[3]), "r"(b0), "r"(b1));
}

// ---------------- K0: conv2 weight fp16 split, pair-packed ----------------
__global__ __launch_bounds__(256) void k0_split_w2(const float* __restrict__ w2)
{
    int i = blockIdx.x * 256 + threadIdx.x;  // 73728 exact
    int co = i & 127;
    int r = i >> 7;              // tap*64 + p
    int p = r & 63, tap = r >> 6;
    int c0 = 2 * p, c1 = c0 + 1;
    float w0 = w2[co * 1152 + c0 * 9 + tap];
    float w1 = w2[co * 1152 + c1 * 9 + tap];
    __half h0 = __float2half_rn(w0);
    __half h1 = __float2half_rn(w1);
    __half l0 = __float2half_rn((w0 - __half2float(h0)) * 2048.0f);
    __half l1 = __float2half_rn((w1 - __half2float(h1)) * 2048.0f);
    uint32_t whi = (uint32_t)__half_as_ushort(h0) | ((uint32_t)__half_as_ushort(h1) << 16);
    uint32_t wlo = (uint32_t)__half_as_ushort(l0) | ((uint32_t)__half_as_ushort(l1) << 16);
    g_w2p[(r * 128 + co) * 2]     = whi;
    g_w2p[(r * 128 + co) * 2 + 1] = wlo;
}

// ---------------- K12: conv1 (1->128) + BN1 + IF1 + 2x2 maxpool, fused ----------------
__global__ __launch_bounds__(256) void k12_conv1_if_pool(
    const float* __restrict__ x, const float* __restrict__ w,
    const float* __restrict__ cb, const float* __restrict__ bg,
    const float* __restrict__ bb, const float* __restrict__ bm,
    const float* __restrict__ bv)
{
    __shared__ float sx[2500];       // 50x50 padded input
    __shared__ float sh[2][2304];    // h planes for the 2 channels
    int b = blockIdx.x >> 6, pair = blockIdx.x & 63;
    int tid = threadIdx.x;
    for (int i = tid; i < 2500; i += 256) sx[i] = 0.0f;
    __syncthreads();
    const float* xp = x + b * 2304;
    for (int i = tid; i < 2304; i += 256) {
        int r = i / 48, q = i - r * 48;
        sx[(r + 1) * 50 + q + 1] = xp[i];
    }
    __syncthreads();
#pragma unroll
    for (int half = 0; half < 2; half++) {
        int c = 2 * pair + half;
        float wr[9];
#pragma unroll
        for (int k = 0; k < 9; k++) wr[k] = w[c * 9 + k];
        float sc = bg[c] * rsqrtf(bv[c] + 1e-5f);
        float sf = (cb[c] - bm[c]) * sc + bb[c];
        for (int p = tid; p < 2304; p += 256) {
            int y = p / 48, xx = p - y * 48;
            const float* sp = sx + y * 50 + xx;
            float a = sp[0] * wr[0] + sp[1] * wr[1] + sp[2] * wr[2]
                    + sp[50] * wr[3] + sp[51] * wr[4] + sp[52] * wr[5]
                    + sp[100] * wr[6] + sp[101] * wr[7] + sp[102] * wr[8];
            sh[half][p] = a * sc + sf;
        }
    }
    __syncthreads();
    for (int p = tid; p < 576; p += 256) {
        int oy = p / 24, ox = p - oy * 24;
        int base = (2 * oy) * 48 + 2 * ox;
        float a0 = sh[0][base], a1 = sh[0][base + 1], a2 = sh[0][base + 48], a3 = sh[0][base + 49];
        float c0 = sh[1][base], c1 = sh[1][base + 1], c2 = sh[1][base + 48], c3 = sh[1][base + 49];
        float va0 = 0.f, va1 = 0.f, va2 = 0.f, va3 = 0.f;
        float vc0 = 0.f, vc1 = 0.f, vc2 = 0.f, vc3 = 0.f;
        int pin = pair * 676 + (oy + 1) * 26 + ox + 1;
#pragma unroll
        for (int t = 0; t < 8; t++) {
            va0 += a0; va1 += a1; va2 += a2; va3 += a3;
            vc0 += c0; vc1 += c1; vc2 += c2; vc3 += c3;
            bool sa0 = va0 >= 1.f, sa1 = va1 >= 1.f, sa2 = va2 >= 1.f, sa3 = va3 >= 1.f;
            bool sc0 = vc0 >= 1.f, sc1 = vc1 >= 1.f, sc2 = vc2 >= 1.f, sc3 = vc3 >= 1.f;
            va0 = sa0 ? 0.f : va0; va1 = sa1 ? 0.f : va1;
            va2 = sa2 ? 0.f : va2; va3 = sa3 ? 0.f : va3;
            vc0 = sc0 ? 0.f : vc0; vc1 = sc1 ? 0.f : vc1;
            vc2 = sc2 ? 0.f : vc2; vc3 = sc3 ? 0.f : vc3;
            bool m0 = sa0 | sa1 | sa2 | sa3;
            bool m1 = sc0 | sc1 | sc2 | sc3;
            uint32_t word = (m0 ? 0x3C00u : 0u) | (m1 ? 0x3C000000u : 0u);
            g_p1h[(t * 32 + b) * 64 * 676 + pin] = word;
        }
    }
}

// ---------------- K3: conv2 + BN2, fp16 mma, full-plane M tile, triple-buffered -------
// Block: (image n, 64-cout half). M = 576 px (full 24x24 plane), 8 warps 4(M)x2(N),
// warp tile m144 x n32 (mf=9). 8 chunks of (8 cin-pairs x 9 taps).
// Buffers: 3 x (A 5408 words [8 planes x 676] + B 9792 words [72 rows x 136]).
__global__ __launch_bounds__(256) void k3_conv2_mma(
    const float* __restrict__ cb, const float* __restrict__ bg,
    const float* __restrict__ bb, const float* __restrict__ bm,
    const float* __restrict__ bv)
{
    extern __shared__ uint32_t dyn[];
    // buffer i at dyn + i*15200: A first 5408 words, B next 9792
    float* sSc = (float*)(dyn + 3 * 15200);  // 64
    float* sSh = sSc + 64;                   // 64

    int n = blockIdx.x;
    int coutbase = blockIdx.y * 64;
    int tid = threadIdx.x;
    int lane = tid & 31, warp = tid >> 5;
    int wm = warp & 3, wn = warp >> 2; // 4 x 2 warp grid
    int qr = lane >> 2, qc = lane & 3;

    if (tid < 64) {
        int oc = coutbase + tid;
        float sc = bg[oc] * rsqrtf(bv[oc] + 1e-5f);
        sSc[tid] = sc;
        sSh[tid] = (cb[oc] - bm[oc]) * sc + bb[oc];
    }

    int offr[9], offr8[9];
#pragma unroll
    for (int mf = 0; mf < 9; mf++) {
        int p = wm * 144 + mf * 16 + qr;
        offr[mf] = (p / 24) * 26 + (p % 24);
        int p8 = p + 8;
        offr8[mf] = (p8 / 24) * 26 + (p8 % 24);
    }

    float acc[9][4][4];
#pragma unroll
    for (int mf = 0; mf < 9; mf++)
#pragma unroll
        for (int nf = 0; nf < 4; nf++)
#pragma unroll
            for (int i = 0; i < 4; i++) acc[mf][nf][i] = 0.f;

    const uint32_t* pbase = g_p1h + n * 64 * 676;

    // stage one chunk (8 cin-pairs, full planes) into buffer buf
    auto issue = [&](int chunk, int buf) {
        uint32_t* sAb = dyn + buf * 15200;
        uint32_t* sBb = sAb + 5408;
        int pb = chunk * 8;  // base cin-pair
        // A: 8 full planes x 676 words = 8 x 169 x 16B
        for (int i = tid; i < 1352; i += 256) {
            int ci = i / 169, q = i - ci * 169;
            __pipeline_memcpy_async(sAb + ci * 676 + q * 4,
                                    pbase + (pb + ci) * 676 + q * 4, 16);
        }
        // B: 72 rows x 32 cout-pairs, 16B each (2 couts = 4 words)
        for (int i = tid; i < 2304; i += 256) {
            int cp2 = i & 31;
            int r = i >> 5;               // tap*8 + pi
            int pi = r & 7, tap = r >> 3;
            __pipeline_memcpy_async(sBb + r * 136 + cp2 * 4,
                                    g_w2p + ((tap * 64 + pb + pi) * 128 + coutbase + cp2 * 2) * 2,
                                    16);
        }
        __pipeline_commit();
    };

    issue(0, 0);
    issue(1, 1);
    int bufc = 0;
    for (int c = 0; c < 8; c++) {
        if (c < 6) {
            issue(c + 2, (c + 2) % 3);
            __pipeline_wait_prior(2);
        } else if (c == 6) {
            __pipeline_wait_prior(1);
        } else {
            __pipeline_wait_prior(0);
        }
        __syncthreads();
        const uint32_t* sAb = dyn + bufc * 15200;
        const uint32_t* sBb = sAb + 5408;
#pragma unroll
        for (int tap = 0; tap < 9; tap++) {
            int toff = (tap / 3) * 26 + (tap % 3);
            // hoist B fragments for this tap (reused by all 9 mf)
            uint2 b0[4], b1[4];
#pragma unroll
            for (int nf = 0; nf < 4; nf++) {
                int ncol = wn * 32 + nf * 8 + qr;
                b0[nf] = *(const uint2*)(sBb + (tap * 8 + qc) * 136 + ncol * 2);
                b1[nf] = *(const uint2*)(sBb + (tap * 8 + qc + 4) * 136 + ncol * 2);
            }
#pragma unroll
            for (int mf = 0; mf < 9; mf++) {
                uint32_t ah[4], al[4];
                ah[0] = sAb[qc * 676 + offr[mf] + toff];
                ah[1] = sAb[qc * 676 + offr8[mf] + toff];
                ah[2] = sAb[(qc + 4) * 676 + offr[mf] + toff];
                ah[3] = sAb[(qc + 4) * 676 + offr8[mf] + toff];
#pragma unroll
                for (int j = 0; j < 4; j++) al[j] = ah[j] & 0x10001000u;
#pragma unroll
                for (int nf = 0; nf < 4; nf++) {
                    mma_f16(acc[mf][nf], ah, b0[nf].x, b1[nf].x);
                    mma_f16(acc[mf][nf], al, b0[nf].y, b1[nf].y);
                }
            }
        }
        __syncthreads();
        bufc = (bufc + 1) % 3;
    }

    // epilogue: BN + scatter to g_c2 [n][cout][576]
    float* op = g_c2 + (n * 128 + coutbase) * 576;
#pragma unroll
    for (int mf = 0; mf < 9; mf++) {
        int p = wm * 144 + mf * 16 + qr;
#pragma unroll
        for (int nf = 0; nf < 4; nf++) {
            int L = wn * 32 + nf * 8 + qc * 2;
            float sc0 = sSc[L], sh0 = sSh[L];
            float sc1 = sSc[L + 1], sh1 = sSh[L + 1];
            op[L * 576 + p]           = acc[mf][nf][0] * sc0 + sh0;
            op[(L + 1) * 576 + p]     = acc[mf][nf][1] * sc1 + sh1;
            op[L * 576 + p + 8]       = acc[mf][nf][2] * sc0 + sh0;
            op[(L + 1) * 576 + p + 8] = acc[mf][nf][3] * sc1 + sh1;
        }
    }
}

// ---------------- K4: IF2 + 2x2 maxpool + flatten, fp16 pair-packed output ----------------
__global__ __launch_bounds__(256) void k4_if2_pool()
{
    int idx = blockIdx.x * 256 + threadIdx.x;  // 294,912 exact
    int oxp = idx % 6;
    int t1 = idx / 6;
    int oy = t1 % 12;
    int t2 = t1 / 12;
    int c = t2 & 127;
    int b = t2 >> 7;
    float va0 = 0.f, va1 = 0.f, va2 = 0.f, va3 = 0.f;
    float vc0 = 0.f, vc1 = 0.f, vc2 = 0.f, vc3 = 0.f;
    int fo = c * 72 + oy * 6 + oxp;
#pragma unroll
    for (int t = 0; t < 8; t++) {
        const float* cp = g_c2 + ((t * 32 + b) * 128 + c) * 576 + (2 * oy) * 24 + 4 * oxp;
        float4 r0 = *(const float4*)cp;
        float4 r1 = *(const float4*)(cp + 24);
        va0 += r0.x; va1 += r0.y; va2 += r1.x; va3 += r1.y;
        vc0 += r0.z; vc1 += r0.w; vc2 += r1.z; vc3 += r1.w;
        bool sa0 = va0 >= 1.f, sa1 = va1 >= 1.f, sa2 = va2 >= 1.f, sa3 = va3 >= 1.f;
        bool sc0 = vc0 >= 1.f, sc1 = vc1 >= 1.f, sc2 = vc2 >= 1.f, sc3 = vc3 >= 1.f;
        va0 = sa0 ? 0.f : va0; va1 = sa1 ? 0.f : va1;
        va2 = sa2 ? 0.f : va2; va3 = sa3 ? 0.f : va3;
        vc0 = sc0 ? 0.f : vc0; vc1 = sc1 ? 0.f : vc1;
        vc2 = sc2 ? 0.f : vc2; vc3 = sc3 ? 0.f : vc3;
        bool m0 = sa0 | sa1 | sa2 | sa3;
        bool m1 = sc0 | sc1 | sc2 | sc3;
        uint32_t word = (m0 ? 0x3C00u : 0u) | (m1 ? 0x3C000000u : 0u);
        g_fh[(t * 32 + b) * 9216 + fo] = word;
    }
}

// ---------------- K5: fc1 GEMM, fp16 mma m16n8k16, split-K=16, cp.async ----------------
__global__ __launch_bounds__(256, 2) void k5_fc1_mma(const float* __restrict__ w1)
{
    extern __shared__ uint32_t dyn5[];
    uint32_t* sA0 = dyn5;                    // 2 x 256*12 words
    float* sB0 = (float*)(dyn5 + 2 * 3072);  // 2 x 64*24 floats

    int n0 = blockIdx.x * 64;
    int z = blockIdx.y;
    int tid = threadIdx.x;
    int lane = tid & 31, warp = tid >> 5;
    int wm = warp & 3, wn = warp >> 2;
    int qr = lane >> 2, qc = lane & 3;

    float acc[4][4][4];
#pragma unroll
    for (int mf = 0; mf < 4; mf++)
#pragma unroll
        for (int nf = 0; nf < 4; nf++)
#pragma unroll
            for (int i = 0; i < 4; i++) acc[mf][nf][i] = 0.f;

    int kbase = z * 1152;

    auto issue = [&](int kc, int buf) {
        int k0 = kbase + kc * 16;
        int kw = k0 >> 1;
        uint32_t* sAb = sA0 + buf * 3072;
        float* sBb = sB0 + buf * 1536;
        for (int v = tid; v < 512; v += 256) {
            int m = v >> 1;
            int hq = (v & 1) * 4;
            __pipeline_memcpy_async(sAb + m * 12 + hq,
                                    g_fh + m * 9216 + kw + hq, 16);
        }
        {
            int nr = tid >> 2;
            int kq = (tid & 3) * 4;
            __pipeline_memcpy_async(sBb + nr * 24 + kq,
                                    w1 + (n0 + nr) * 18432 + k0 + kq, 16);
        }
        __pipeline_commit();
    };

    issue(0, 0);
    for (int kc = 0; kc < 72; kc++) {
        if (kc < 71) {
            issue(kc + 1, (kc + 1) & 1);
            __pipeline_wait_prior(1);
        } else {
            __pipeline_wait_prior(0);
        }
        __syncthreads();
        const uint32_t* sAb = sA0 + (kc & 1) * 3072;
        const float* sBb = sB0 + (kc & 1) * 1536;
        uint32_t ah[4][4], al[4][4];
#pragma unroll
        for (int mf = 0; mf < 4; mf++) {
            int m = wm * 64 + mf * 16 + qr;
            ah[mf][0] = sAb[m * 12 + qc];
            ah[mf][1] = sAb[(m + 8) * 12 + qc];
            ah[mf][2] = sAb[m * 12 + qc + 4];
            ah[mf][3] = sAb[(m + 8) * 12 + qc + 4];
#pragma unroll
            for (int j = 0; j < 4; j++) al[mf][j] = ah[mf][j] & 0x10001000u;
        }
#pragma unroll
        for (int nf = 0; nf < 4; nf++) {
            int nn = wn * 32 + nf * 8 + qr;
            float2 p0 = *(const float2*)(sBb + nn * 24 + 2 * qc);
            float2 p1 = *(const float2*)(sBb + nn * 24 + 2 * qc + 8);
            __half2 h0 = __float22half2_rn(p0);
            __half2 h1 = __float22half2_rn(p1);
            float2 h0f = __half22float2(h0);
            float2 h1f = __half22float2(h1);
            __half2 l0 = __float22half2_rn(
                make_float2((p0.x - h0f.x) * 2048.0f, (p0.y - h0f.y) * 2048.0f));
            __half2 l1 = __float22half2_rn(
                make_float2((p1.x - h1f.x) * 2048.0f, (p1.y - h1f.y) * 2048.0f));
            uint32_t bh0 = *(uint32_t*)&h0, bh1 = *(uint32_t*)&h1;
            uint32_t bl0 = *(uint32_t*)&l0, bl1 = *(uint32_t*)&l1;
#pragma unroll
            for (int mf = 0; mf < 4; mf++) {
                mma_f16(acc[mf][nf], ah[mf], bh0, bh1);
                mma_f16(acc[mf][nf], al[mf], bl0, bl1);
            }
        }
        __syncthreads();
    }

    float* op = g_y1p + z * 294912;
#pragma unroll
    for (int mf = 0; mf < 4; mf++) {
        int m = wm * 64 + mf * 16 + qr;
#pragma unroll
        for (int nf = 0; nf < 4; nf++) {
            int nn = n0 + wn * 32 + nf * 8 + qc * 2;
            op[m * 1152 + nn]           = acc[mf][nf][0];
            op[m * 1152 + nn + 1]       = acc[mf][nf][1];
            op[(m + 8) * 1152 + nn]     = acc[mf][nf][2];
            op[(m + 8) * 1152 + nn + 1] = acc[mf][nf][3];
        }
    }
}

// ---------------- K6: reduce split-K(16) + bias + LIF1 ----------------
__global__ __launch_bounds__(256) void k6_lif1(const float* __restrict__ bias)
{
    int idx = blockIdx.x * 256 + threadIdx.x;  // 36,864 exact
    int o = idx % 1152, b = idx / 1152;
    float bi = bias[o];
    float v = 0.f;
#pragma unroll
    for (int t = 0; t < 8; t++) {
        int row = (t * 32 + b) * 1152 + o;
        float xx = bi;
#pragma unroll
        for (int z = 0; z < 16; z++) xx += g_y1p[z * 294912 + row];
        v += (xx - v) * 0.5f;
        float s = v >= 1.f ? 1.f : 0.f;
        g_l1[row] = s;
        v = v >= 1.f ? 0.f : v;
    }
}

// ---------------- K7: fc2, blocked (4 rows per block, rows in smem) ----------------
__global__ __launch_bounds__(128) void k7_fc2(const float* __restrict__ w,
                                              const float* __restrict__ bias)
{
    __shared__ float srow[4 * 1152];
    int r0 = blockIdx.x * 4;
    int o = threadIdx.x;
    for (int i = o; i < 4608; i += 128) srow[i] = g_l1[r0 * 1152 + i];
    __syncthreads();
    float a0 = 0.f, a1 = 0.f, a2 = 0.f, a3 = 0.f;
    const float4* wp = (const float4*)(w + o * 1152);
#pragma unroll 4
    for (int k = 0; k < 288; k++) {
        float4 wv = wp[k];
        float4 s0 = *(const float4*)&srow[4 * k];
        float4 s1 = *(const float4*)&srow[1152 + 4 * k];
        float4 s2 = *(const float4*)&srow[2304 + 4 * k];
        float4 s3 = *(const float4*)&srow[3456 + 4 * k];
        a0 += s0.x * wv.x + s0.y * wv.y + s0.z * wv.z + s0.w * wv.w;
        a1 += s1.x * wv.x + s1.y * wv.y + s1.z * wv.z + s1.w * wv.w;
        a2 += s2.x * wv.x + s2.y * wv.y + s2.z * wv.z + s2.w * wv.w;
        a3 += s3.x * wv.x + s3.y * wv.y + s3.z * wv.z + s3.w * wv.w;
    }
    float bi = bias[o];
    g_y2[(r0 + 0) * 128 + o] = a0 + bi;
    g_y2[(r0 + 1) * 128 + o] = a1 + bi;
    g_y2[(r0 + 2) * 128 + o] = a2 + bi;
    g_y2[(r0 + 3) * 128 + o] = a3 + bi;
}

// ---------------- K8: LIF2 ----------------
__global__ __launch_bounds__(256) void k8_lif2()
{
    int idx = blockIdx.x * 256 + threadIdx.x;  // 4096 exact
    int o = idx & 127, b = idx >> 7;
    float v = 0.f;
#pragma unroll
    for (int t = 0; t < 8; t++) {
        int row = (t * 32 + b) * 128 + o;
        float xx = g_y2[row];
        v += (xx - v) * 0.5f;
        float s = v >= 1.f ? 1.f : 0.f;
        g_l2[row] = s;
        v = v >= 1.f ? 0.f : v;
    }
}

// ---------------- K9: fc3 + LIF3 + mean over T ----------------
__global__ __launch_bounds__(256) void k9_fc3(const float* __restrict__ w,
                                              const float* __restrict__ bias,
                                              float* __restrict__ out)
{
    int idx = threadIdx.x;
    if (idx >= 224) return;
    int o = idx % 7, b = idx / 7;
    const float4* wp = (const float4*)(w + o * 128);
    float v = 0.f, accm = 0.f;
    float bi = bias[o];
    for (int t = 0; t < 8; t++) {
        const float4* lp = (const float4*)(g_l2 + (t * 32 + b) * 128);
        float y = 0.f;
#pragma unroll
        for (int k = 0; k < 32; k++) {
            float4 a = lp[k], ww = wp[k];
            y += a.x * ww.x + a.y * ww.y + a.z * ww.z + a.w * ww.w;
        }
        y += bi;
        v += (y - v) * 0.5f;
        float s = v >= 1.f ? 1.f : 0.f;
        accm += s;
        v = v >= 1.f ? 0.f : v;
    }
    out[b * 7 + o] = accm * 0.125f;
}

// ---------------- launch ----------------
#define K3_SMEM ((3 * 15200 + 128) * 4)      // 182912 B
#define K5_SMEM ((2 * 3072 + 2 * 1536) * 4)  // 36864 B

extern "C" void kernel_launch(void* const* d_in, const int* in_sizes, int n_in,
                              void* d_out, int out_size)
{
    const float* x       = (const float*)d_in[0];
    const float* conv1_w = (const float*)d_in[1];
    const float* conv1_b = (const float*)d_in[2];
    const float* bn1_g   = (const float*)d_in[3];
    const float* bn1_b   = (const float*)d_in[4];
    const float* bn1_m   = (const float*)d_in[5];
    const float* bn1_v   = (const float*)d_in[6];
    const float* conv2_w = (const float*)d_in[7];
    const float* conv2_b = (const float*)d_in[8];
    const float* bn2_g   = (const float*)d_in[9];
    const float* bn2_b   = (const float*)d_in[10];
    const float* bn2_m   = (const float*)d_in[11];
    const float* bn2_v   = (const float*)d_in[12];
    const float* fc1_w   = (const float*)d_in[13];
    const float* fc1_b   = (const float*)d_in[14];
    const float* fc2_w   = (const float*)d_in[15];
    const float* fc2_b   = (const float*)d_in[16];
    const float* fc3_w   = (const float*)d_in[17];
    const float* fc3_b   = (const float*)d_in[18];

    static bool attr_done = false;
    if (!attr_done) {
        cudaFuncSetAttribute(k3_conv2_mma,
                             cudaFuncAttributeMaxDynamicSharedMemorySize, K3_SMEM);
        cudaFuncSetAttribute(k3_conv2_mma,
                             cudaFuncAttributePreferredSharedMemoryCarveout, 100);
        cudaFuncSetAttribute(k5_fc1_mma,
                             cudaFuncAttributeMaxDynamicSharedMemorySize, K5_SMEM);
        cudaFuncSetAttribute(k5_fc1_mma,
                             cudaFuncAttributePreferredSharedMemoryCarveout, 100);
        attr_done = true;
    }

    // zero padded p1 borders (interior overwritten by K12)
    void* p1ptr = nullptr;
    cudaGetSymbolAddress(&p1ptr, g_p1h);
    cudaMemsetAsync(p1ptr, 0, sizeof(g_p1h));

    k0_split_w2<<<288, 256>>>(conv2_w);
    k12_conv1_if_pool<<<2048, 256>>>(x, conv1_w, conv1_b, bn1_g, bn1_b, bn1_m, bn1_v);
    dim3 g3(NTB, 2);
    k3_conv2_mma<<<g3, 256, K3_SMEM>>>(conv2_b, bn2_g, bn2_b, bn2_m, bn2_v);
    k4_if2_pool<<<1152, 256>>>();
    dim3 g5(18, 16);
    k5_fc1_mma<<<g5, 256, K5_SMEM>>>(fc1_w);
    k6_lif1<<<144, 256>>>(fc1_b);
    k7_fc2<<<64, 128>>>(fc2_w, fc2_b);
    k8_lif2<<<16, 256>>>();
    k9_fc3<<<1, 256>>>(fc3_w, fc3_b, (float*)d_out);
}

// round 11
// speedup vs baseline: 1.0939x; 1.0939x over previous
#include <cuda_runtime.h>
#include <cuda_pipeline.h>
#include <cuda_fp16.h>
#include <cstdint>

// SJCSNN spiking CNN forward, T=8, B=32, out [32,7] f32.
// conv2 AND fc1: fp16 mma.m16n8k16, scaled 2-term weight split, single fp32 acc
//   (spikes {0,1} exact in fp16; lo-term A = spikes*2^-11 via bit-mask trick,
//    lo-term B = (w - fp16(w)) * 2^11).
// R11: k3 reverted to R9 config (192px tile, 2 CTAs/SM — R10's 576px tile
// spilled registers and regressed). Border zeroing fused into k12; no memset.

#define NTB 256  // T*B

// ---- scratch (device globals; no allocations) ----
__device__ __align__(16) uint32_t g_p1h[NTB * 64 * 676];   // IF1+pool spikes, fp16 pair-packed, PADDED 26x26
__device__ __align__(16) float g_c2[NTB * 128 * 24 * 24];  // conv2+bn2 output
__device__ __align__(16) uint32_t g_fh[NTB * 9216];        // IF2+pool spikes, fp16 pair-packed flat
__device__ float g_y1p[16 * NTB * 1152];                   // fc1 split-K partials (16)
__device__ __align__(16) float g_l1[NTB * 1152];           // LIF1 spikes
__device__ float g_y2[NTB * 128];                          // fc2 output
__device__ float g_l2[NTB * 128];                          // LIF2 spikes
// conv2 weights fp16 split: [tap(9)][cinpair(64)][cout(128)][hi,lo] as half2 words
__device__ __align__(16) uint32_t g_w2p[9 * 64 * 128 * 2];

// ---------------- mma helper ----------------
__device__ __forceinline__ void mma_f16(float c[4], const uint32_t a[4],
                                        uint32_t b0, uint32_t b1) {
    asm volatile(
        "mma.sync.aligned.m16n8k16.row.col.f32.f16.f16.f32 "
        "{%0,%1,%2,%3}, {%4,%5,%6,%7}, {%8,%9}, {%0,%1,%2,%3};"
        : "+f"(c[0]), "+f"(c[1]), "+f"(c[2]), "+f"(c[3])
        : "r"(a[0]), "r"(a[1]), "r"(a[2]), "r"(a[3]), "r"(b0), "r"(b1));
}

// ---------------- K0: conv2 weight fp16 split, pair-packed ----------------
__global__ __launch_bounds__(256) void k0_split_w2(const float* __restrict__ w2)
{
    int i = blockIdx.x * 256 + threadIdx.x;  // 73728 exact
    int co = i & 127;
    int r = i >> 7;              // tap*64 + p
    int p = r & 63, tap = r >> 6;
    int c0 = 2 * p, c1 = c0 + 1;
    float w0 = w2[co * 1152 + c0 * 9 + tap];
    float w1 = w2[co * 1152 + c1 * 9 + tap];
    __half h0 = __float2half_rn(w0);
    __half h1 = __float2half_rn(w1);
    __half l0 = __float2half_rn((w0 - __half2float(h0)) * 2048.0f);
    __half l1 = __float2half_rn((w1 - __half2float(h1)) * 2048.0f);
    uint32_t whi = (uint32_t)__half_as_ushort(h0) | ((uint32_t)__half_as_ushort(h1) << 16);
    uint32_t wlo = (uint32_t)__half_as_ushort(l0) | ((uint32_t)__half_as_ushort(l1) << 16);
    g_w2p[(r * 128 + co) * 2]     = whi;
    g_w2p[(r * 128 + co) * 2 + 1] = wlo;
}

// ---------------- K12: conv1 (1->128) + BN1 + IF1 + 2x2 maxpool, fused ----------------
// Also zeroes the 26x26 plane borders for its 8 (t) planes (replaces global memset).
__global__ __launch_bounds__(256) void k12_conv1_if_pool(
    const float* __restrict__ x, const float* __restrict__ w,
    const float* __restrict__ cb, const float* __restrict__ bg,
    const float* __restrict__ bb, const float* __restrict__ bm,
    const float* __restrict__ bv)
{
    __shared__ float sx[2500];       // 50x50 padded input
    __shared__ float sh[2][2304];    // h planes for the 2 channels
    int b = blockIdx.x >> 6, pair = blockIdx.x & 63;
    int tid = threadIdx.x;
    for (int i = tid; i < 2500; i += 256) sx[i] = 0.0f;

    // zero plane borders (100 words/plane x 8 t-planes), interior written below
    {
        int pb = pair * 676;
#pragma unroll
        for (int ii = 0; ii < 4; ii++) {
            int i = tid + ii * 256;
            if (i < 800) {
                int t = i >> 7;           // 0..7 (i/100... use /100)
                t = i / 100;
                int e = i - t * 100;
                int off;
                if (e < 26) off = e;                       // row 0
                else if (e < 52) off = 25 * 26 + (e - 26); // row 25
                else if (e < 76) off = (e - 52 + 1) * 26;  // col 0, rows 1..24
                else off = (e - 76 + 1) * 26 + 25;         // col 25, rows 1..24
                g_p1h[(t * 32 + b) * 64 * 676 + pb + off] = 0u;
            }
        }
    }
    __syncthreads();
    const float* xp = x + b * 2304;
    for (int i = tid; i < 2304; i += 256) {
        int r = i / 48, q = i - r * 48;
        sx[(r + 1) * 50 + q + 1] = xp[i];
    }
    __syncthreads();
#pragma unroll
    for (int half = 0; half < 2; half++) {
        int c = 2 * pair + half;
        float wr[9];
#pragma unroll
        for (int k = 0; k < 9; k++) wr[k] = w[c * 9 + k];
        float sc = bg[c] * rsqrtf(bv[c] + 1e-5f);
        float sf = (cb[c] - bm[c]) * sc + bb[c];
        for (int p = tid; p < 2304; p += 256) {
            int y = p / 48, xx = p - y * 48;
            const float* sp = sx + y * 50 + xx;
            float a = sp[0] * wr[0] + sp[1] * wr[1] + sp[2] * wr[2]
                    + sp[50] * wr[3] + sp[51] * wr[4] + sp[52] * wr[5]
                    + sp[100] * wr[6] + sp[101] * wr[7] + sp[102] * wr[8];
            sh[half][p] = a * sc + sf;
        }
    }
    __syncthreads();
    for (int p = tid; p < 576; p += 256) {
        int oy = p / 24, ox = p - oy * 24;
        int base = (2 * oy) * 48 + 2 * ox;
        float a0 = sh[0][base], a1 = sh[0][base + 1], a2 = sh[0][base + 48], a3 = sh[0][base + 49];
        float c0 = sh[1][base], c1 = sh[1][base + 1], c2 = sh[1][base + 48], c3 = sh[1][base + 49];
        float va0 = 0.f, va1 = 0.f, va2 = 0.f, va3 = 0.f;
        float vc0 = 0.f, vc1 = 0.f, vc2 = 0.f, vc3 = 0.f;
        int pin = pair * 676 + (oy + 1) * 26 + ox + 1;
#pragma unroll
        for (int t = 0; t < 8; t++) {
            va0 += a0; va1 += a1; va2 += a2; va3 += a3;
            vc0 += c0; vc1 += c1; vc2 += c2; vc3 += c3;
            bool sa0 = va0 >= 1.f, sa1 = va1 >= 1.f, sa2 = va2 >= 1.f, sa3 = va3 >= 1.f;
            bool sc0 = vc0 >= 1.f, sc1 = vc1 >= 1.f, sc2 = vc2 >= 1.f, sc3 = vc3 >= 1.f;
            va0 = sa0 ? 0.f : va0; va1 = sa1 ? 0.f : va1;
            va2 = sa2 ? 0.f : va2; va3 = sa3 ? 0.f : va3;
            vc0 = sc0 ? 0.f : vc0; vc1 = sc1 ? 0.f : vc1;
            vc2 = sc2 ? 0.f : vc2; vc3 = sc3 ? 0.f : vc3;
            bool m0 = sa0 | sa1 | sa2 | sa3;
            bool m1 = sc0 | sc1 | sc2 | sc3;
            uint32_t word = (m0 ? 0x3C00u : 0u) | (m1 ? 0x3C000000u : 0u);
            g_p1h[(t * 32 + b) * 64 * 676 + pin] = word;
        }
    }
}

// ---------------- K3: conv2 + BN2, fp16 mma m16n8k16, cp.async double-buffered --------
// (R9 config: 192px M tile, 64-cout N tile, 8 warps 4Mx2N, 2 CTAs/SM.)
__global__ __launch_bounds__(256, 2) void k3_conv2_mma(
    const float* __restrict__ cb, const float* __restrict__ bg,
    const float* __restrict__ bb, const float* __restrict__ bm,
    const float* __restrict__ bv)
{
    extern __shared__ uint32_t dyn[];
    uint32_t* sA0 = dyn;                       // 2 x 2080 words (8 pair-planes x 260)
    uint32_t* sB0 = dyn + 4160;                // 2 x 9792 words (72 rows x 136)
    float* sSc = (float*)(dyn + 4160 + 19584); // 64
    float* sSh = sSc + 64;                     // 64

    int n = blockIdx.x;
    int y0g = blockIdx.y;              // 0..2  -> rows y0g*8 .. +7
    int coutbase = blockIdx.z * 64;    // 0 or 64
    int tid = threadIdx.x;
    int lane = tid & 31, warp = tid >> 5;
    int wm = warp & 3, wn = warp >> 2; // 4 x 2 warp grid
    int qr = lane >> 2, qc = lane & 3;

    if (tid < 64) {
        int oc = coutbase + tid;
        float sc = bg[oc] * rsqrtf(bv[oc] + 1e-5f);
        sSc[tid] = sc;
        sSh[tid] = (cb[oc] - bm[oc]) * sc + bb[oc];
    }

    int offr[3], offr8[3];
#pragma unroll
    for (int mf = 0; mf < 3; mf++) {
        int p = wm * 48 + mf * 16 + qr;
        offr[mf] = (p / 24) * 26 + (p % 24);
        int p8 = p + 8;
        offr8[mf] = (p8 / 24) * 26 + (p8 % 24);
    }

    float acc[3][4][4];
#pragma unroll
    for (int mf = 0; mf < 3; mf++)
#pragma unroll
        for (int nf = 0; nf < 4; nf++)
#pragma unroll
            for (int i = 0; i < 4; i++) acc[mf][nf][i] = 0.f;

    int y0 = y0g * 8;
    const uint32_t* pbase = g_p1h + n * 64 * 676 + y0 * 26;

    auto issue = [&](int chunk, int buf) {
        uint32_t* sAb = sA0 + buf * 2080;
        uint32_t* sBb = sB0 + buf * 9792;
        int pb = chunk * 8;  // base cin-pair
        for (int i = tid; i < 520; i += 256) {
            int ci = i / 65, q = i - ci * 65;
            __pipeline_memcpy_async(sAb + ci * 260 + q * 4,
                                    pbase + (pb + ci) * 676 + q * 4, 16);
        }
        // B: 72 rows x 32 cout-pairs, 16B each (2 couts = 4 words)
        for (int i = tid; i < 2304; i += 256) {
            int cp2 = i & 31;
            int r = i >> 5;               // tap*8 + pi
            int pi = r & 7, tap = r >> 3;
            __pipeline_memcpy_async(sBb + r * 136 + cp2 * 4,
                                    g_w2p + ((tap * 64 + pb + pi) * 128 + coutbase + cp2 * 2) * 2,
                                    16);
        }
        __pipeline_commit();
    };

    issue(0, 0);
    for (int c = 0; c < 8; c++) {
        if (c < 7) {
            issue(c + 1, (c + 1) & 1);
            __pipeline_wait_prior(1);
        } else {
            __pipeline_wait_prior(0);
        }
        __syncthreads();
        const uint32_t* sAb = sA0 + (c & 1) * 2080;
        const uint32_t* sBb = sB0 + (c & 1) * 9792;
#pragma unroll
        for (int tap = 0; tap < 9; tap++) {
            int toff = (tap / 3) * 26 + (tap % 3);
            uint32_t ah[3][4], al[3][4];
#pragma unroll
            for (int mf = 0; mf < 3; mf++) {
                ah[mf][0] = sAb[qc * 260 + offr[mf] + toff];
                ah[mf][1] = sAb[qc * 260 + offr8[mf] + toff];
                ah[mf][2] = sAb[(qc + 4) * 260 + offr[mf] + toff];
                ah[mf][3] = sAb[(qc + 4) * 260 + offr8[mf] + toff];
#pragma unroll
                for (int j = 0; j < 4; j++) al[mf][j] = ah[mf][j] & 0x10001000u;
            }
#pragma unroll
            for (int nf = 0; nf < 4; nf++) {
                int ncol = wn * 32 + nf * 8 + qr;
                uint2 b0 = *(const uint2*)(sBb + (tap * 8 + qc) * 136 + ncol * 2);
                uint2 b1 = *(const uint2*)(sBb + (tap * 8 + qc + 4) * 136 + ncol * 2);
#pragma unroll
                for (int mf = 0; mf < 3; mf++) {
                    mma_f16(acc[mf][nf], ah[mf], b0.x, b1.x);
                    mma_f16(acc[mf][nf], al[mf], b0.y, b1.y);
                }
            }
        }
        __syncthreads();
    }

    float* op = g_c2 + (n * 128 + coutbase) * 576 + y0g * 192;
#pragma unroll
    for (int mf = 0; mf < 3; mf++) {
        int p = wm * 48 + mf * 16 + qr;
#pragma unroll
        for (int nf = 0; nf < 4; nf++) {
            int L = wn * 32 + nf * 8 + qc * 2;
            float sc0 = sSc[L], sh0 = sSh[L];
            float sc1 = sSc[L + 1], sh1 = sSh[L + 1];
            op[L * 576 + p]           = acc[mf][nf][0] * sc0 + sh0;
            op[(L + 1) * 576 + p]     = acc[mf][nf][1] * sc1 + sh1;
            op[L * 576 + p + 8]       = acc[mf][nf][2] * sc0 + sh0;
            op[(L + 1) * 576 + p + 8] = acc[mf][nf][3] * sc1 + sh1;
        }
    }
}

// ---------------- K4: IF2 + 2x2 maxpool + flatten, fp16 pair-packed output ----------------
__global__ __launch_bounds__(256) void k4_if2_pool()
{
    int idx = blockIdx.x * 256 + threadIdx.x;  // 294,912 exact
    int oxp = idx % 6;
    int t1 = idx / 6;
    int oy = t1 % 12;
    int t2 = t1 / 12;
    int c = t2 & 127;
    int b = t2 >> 7;
    float va0 = 0.f, va1 = 0.f, va2 = 0.f, va3 = 0.f;
    float vc0 = 0.f, vc1 = 0.f, vc2 = 0.f, vc3 = 0.f;
    int fo = c * 72 + oy * 6 + oxp;
#pragma unroll
    for (int t = 0; t < 8; t++) {
        const float* cp = g_c2 + ((t * 32 + b) * 128 + c) * 576 + (2 * oy) * 24 + 4 * oxp;
        float4 r0 = *(const float4*)cp;
        float4 r1 = *(const float4*)(cp + 24);
        va0 += r0.x; va1 += r0.y; va2 += r1.x; va3 += r1.y;
        vc0 += r0.z; vc1 += r0.w; vc2 += r1.z; vc3 += r1.w;
        bool sa0 = va0 >= 1.f, sa1 = va1 >= 1.f, sa2 = va2 >= 1.f, sa3 = va3 >= 1.f;
        bool sc0 = vc0 >= 1.f, sc1 = vc1 >= 1.f, sc2 = vc2 >= 1.f, sc3 = vc3 >= 1.f;
        va0 = sa0 ? 0.f : va0; va1 = sa1 ? 0.f : va1;
        va2 = sa2 ? 0.f : va2; va3 = sa3 ? 0.f : va3;
        vc0 = sc0 ? 0.f : vc0; vc1 = sc1 ? 0.f : vc1;
        vc2 = sc2 ? 0.f : vc2; vc3 = sc3 ? 0.f : vc3;
        bool m0 = sa0 | sa1 | sa2 | sa3;
        bool m1 = sc0 | sc1 | sc2 | sc3;
        uint32_t word = (m0 ? 0x3C00u : 0u) | (m1 ? 0x3C000000u : 0u);
        g_fh[(t * 32 + b) * 9216 + fo] = word;
    }
}

// ---------------- K5: fc1 GEMM, fp16 mma m16n8k16, split-K=16, cp.async ----------------
__global__ __launch_bounds__(256, 2) void k5_fc1_mma(const float* __restrict__ w1)
{
    extern __shared__ uint32_t dyn5[];
    uint32_t* sA0 = dyn5;                    // 2 x 256*12 words
    float* sB0 = (float*)(dyn5 + 2 * 3072);  // 2 x 64*24 floats

    int n0 = blockIdx.x * 64;
    int z = blockIdx.y;
    int tid = threadIdx.x;
    int lane = tid & 31, warp = tid >> 5;
    int wm = warp & 3, wn = warp >> 2;
    int qr = lane >> 2, qc = lane & 3;

    float acc[4][4][4];
#pragma unroll
    for (int mf = 0; mf < 4; mf++)
#pragma unroll
        for (int nf = 0; nf < 4; nf++)
#pragma unroll
            for (int i = 0; i < 4; i++) acc[mf][nf][i] = 0.f;

    int kbase = z * 1152;

    auto issue = [&](int kc, int buf) {
        int k0 = kbase + kc * 16;
        int kw = k0 >> 1;
        uint32_t* sAb = sA0 + buf * 3072;
        float* sBb = sB0 + buf * 1536;
        for (int v = tid; v < 512; v += 256) {
            int m = v >> 1;
            int hq = (v & 1) * 4;
            __pipeline_memcpy_async(sAb + m * 12 + hq,
                                    g_fh + m * 9216 + kw + hq, 16);
        }
        {
            int nr = tid >> 2;
            int kq = (tid & 3) * 4;
            __pipeline_memcpy_async(sBb + nr * 24 + kq,
                                    w1 + (n0 + nr) * 18432 + k0 + kq, 16);
        }
        __pipeline_commit();
    };

    issue(0, 0);
    for (int kc = 0; kc < 72; kc++) {
        if (kc < 71) {
            issue(kc + 1, (kc + 1) & 1);
            __pipeline_wait_prior(1);
        } else {
            __pipeline_wait_prior(0);
        }
        __syncthreads();
        const uint32_t* sAb = sA0 + (kc & 1) * 3072;
        const float* sBb = sB0 + (kc & 1) * 1536;
        uint32_t ah[4][4], al[4][4];
#pragma unroll
        for (int mf = 0; mf < 4; mf++) {
            int m = wm * 64 + mf * 16 + qr;
            ah[mf][0] = sAb[m * 12 + qc];
            ah[mf][1] = sAb[(m + 8) * 12 + qc];
            ah[mf][2] = sAb[m * 12 + qc + 4];
            ah[mf][3] = sAb[(m + 8) * 12 + qc + 4];
#pragma unroll
            for (int j = 0; j < 4; j++) al[mf][j] = ah[mf][j] & 0x10001000u;
        }
#pragma unroll
        for (int nf = 0; nf < 4; nf++) {
            int nn = wn * 32 + nf * 8 + qr;
            float2 p0 = *(const float2*)(sBb + nn * 24 + 2 * qc);
            float2 p1 = *(const float2*)(sBb + nn * 24 + 2 * qc + 8);
            __half2 h0 = __float22half2_rn(p0);
            __half2 h1 = __float22half2_rn(p1);
            float2 h0f = __half22float2(h0);
            float2 h1f = __half22float2(h1);
            __half2 l0 = __float22half2_rn(
                make_float2((p0.x - h0f.x) * 2048.0f, (p0.y - h0f.y) * 2048.0f));
            __half2 l1 = __float22half2_rn(
                make_float2((p1.x - h1f.x) * 2048.0f, (p1.y - h1f.y) * 2048.0f));
            uint32_t bh0 = *(uint32_t*)&h0, bh1 = *(uint32_t*)&h1;
            uint32_t bl0 = *(uint32_t*)&l0, bl1 = *(uint32_t*)&l1;
#pragma unroll
            for (int mf = 0; mf < 4; mf++) {
                mma_f16(acc[mf][nf], ah[mf], bh0, bh1);
                mma_f16(acc[mf][nf], al[mf], bl0, bl1);
            }
        }
        __syncthreads();
    }

    float* op = g_y1p + z * 294912;
#pragma unroll
    for (int mf = 0; mf < 4; mf++) {
        int m = wm * 64 + mf * 16 + qr;
#pragma unroll
        for (int nf = 0; nf < 4; nf++) {
            int nn = n0 + wn * 32 + nf * 8 + qc * 2;
            op[m * 1152 + nn]           = acc[mf][nf][0];
            op[m * 1152 + nn + 1]       = acc[mf][nf][1];
            op[(m + 8) * 1152 + nn]     = acc[mf][nf][2];
            op[(m + 8) * 1152 + nn + 1] = acc[mf][nf][3];
        }
    }
}

// ---------------- K6: reduce split-K(16) + bias + LIF1 ----------------
__global__ __launch_bounds__(256) void k6_lif1(const float* __restrict__ bias)
{
    int idx = blockIdx.x * 256 + threadIdx.x;  // 36,864 exact
    int o = idx % 1152, b = idx / 1152;
    float bi = bias[o];
    float v = 0.f;
#pragma unroll
    for (int t = 0; t < 8; t++) {
        int row = (t * 32 + b) * 1152 + o;
        float xx = bi;
#pragma unroll
        for (int z = 0; z < 16; z++) xx += g_y1p[z * 294912 + row];
        v += (xx - v) * 0.5f;
        float s = v >= 1.f ? 1.f : 0.f;
        g_l1[row] = s;
        v = v >= 1.f ? 0.f : v;
    }
}

// ---------------- K7: fc2, blocked (4 rows per block, rows in smem) ----------------
__global__ __launch_bounds__(128) void k7_fc2(const float* __restrict__ w,
                                              const float* __restrict__ bias)
{
    __shared__ float srow[4 * 1152];
    int r0 = blockIdx.x * 4;
    int o = threadIdx.x;
    for (int i = o; i < 4608; i += 128) srow[i] = g_l1[r0 * 1152 + i];
    __syncthreads();
    float a0 = 0.f, a1 = 0.f, a2 = 0.f, a3 = 0.f;
    const float4* wp = (const float4*)(w + o * 1152);
#pragma unroll 4
    for (int k = 0; k < 288; k++) {
        float4 wv = wp[k];
        float4 s0 = *(const float4*)&srow[4 * k];
        float4 s1 = *(const float4*)&srow[1152 + 4 * k];
        float4 s2 = *(const float4*)&srow[2304 + 4 * k];
        float4 s3 = *(const float4*)&srow[3456 + 4 * k];
        a0 += s0.x * wv.x + s0.y * wv.y + s0.z * wv.z + s0.w * wv.w;
        a1 += s1.x * wv.x + s1.y * wv.y + s1.z * wv.z + s1.w * wv.w;
        a2 += s2.x * wv.x + s2.y * wv.y + s2.z * wv.z + s2.w * wv.w;
        a3 += s3.x * wv.x + s3.y * wv.y + s3.z * wv.z + s3.w * wv.w;
    }
    float bi = bias[o];
    g_y2[(r0 + 0) * 128 + o] = a0 + bi;
    g_y2[(r0 + 1) * 128 + o] = a1 + bi;
    g_y2[(r0 + 2) * 128 + o] = a2 + bi;
    g_y2[(r0 + 3) * 128 + o] = a3 + bi;
}

// ---------------- K8: LIF2 ----------------
__global__ __launch_bounds__(256) void k8_lif2()
{
    int idx = blockIdx.x * 256 + threadIdx.x;  // 4096 exact
    int o = idx & 127, b = idx >> 7;
    float v = 0.f;
#pragma unroll
    for (int t = 0; t < 8; t++) {
        int row = (t * 32 + b) * 128 + o;
        float xx = g_y2[row];
        v += (xx - v) * 0.5f;
        float s = v >= 1.f ? 1.f : 0.f;
        g_l2[row] = s;
        v = v >= 1.f ? 0.f : v;
    }
}

// ---------------- K9: fc3 + LIF3 + mean over T ----------------
__global__ __launch_bounds__(256) void k9_fc3(const float* __restrict__ w,
                                              const float* __restrict__ bias,
                                              float* __restrict__ out)
{
    int idx = threadIdx.x;
    if (idx >= 224) return;
    int o = idx % 7, b = idx / 7;
    const float4* wp = (const float4*)(w + o * 128);
    float v = 0.f, accm = 0.f;
    float bi = bias[o];
    for (int t = 0; t < 8; t++) {
        const float4* lp = (const float4*)(g_l2 + (t * 32 + b) * 128);
        float y = 0.f;
#pragma unroll
        for (int k = 0; k < 32; k++) {
            float4 a = lp[k], ww = wp[k];
            y += a.x * ww.x + a.y * ww.y + a.z * ww.z + a.w * ww.w;
        }
        y += bi;
        v += (y - v) * 0.5f;
        float s = v >= 1.f ? 1.f : 0.f;
        accm += s;
        v = v >= 1.f ? 0.f : v;
    }
    out[b * 7 + o] = accm * 0.125f;
}

// ---------------- launch ----------------
#define K3_SMEM ((4160 + 19584 + 128) * 4)   // 95488 B
#define K5_SMEM ((2 * 3072 + 2 * 1536) * 4)  // 36864 B

extern "C" void kernel_launch(void* const* d_in, const int* in_sizes, int n_in,
                              void* d_out, int out_size)
{
    const float* x       = (const float*)d_in[0];
    const float* conv1_w = (const float*)d_in[1];
    const float* conv1_b = (const float*)d_in[2];
    const float* bn1_g   = (const float*)d_in[3];
    const float* bn1_b   = (const float*)d_in[4];
    const float* bn1_m   = (const float*)d_in[5];
    const float* bn1_v   = (const float*)d_in[6];
    const float* conv2_w = (const float*)d_in[7];
    const float* conv2_b = (const float*)d_in[8];
    const float* bn2_g   = (const float*)d_in[9];
    const float* bn2_b   = (const float*)d_in[10];
    const float* bn2_m   = (const float*)d_in[11];
    const float* bn2_v   = (const float*)d_in[12];
    const float* fc1_w   = (const float*)d_in[13];
    const float* fc1_b   = (const float*)d_in[14];
    const float* fc2_w   = (const float*)d_in[15];
    const float* fc2_b   = (const float*)d_in[16];
    const float* fc3_w   = (const float*)d_in[17];
    const float* fc3_b   = (const float*)d_in[18];

    static bool attr_done = false;
    if (!attr_done) {
        cudaFuncSetAttribute(k3_conv2_mma,
                             cudaFuncAttributeMaxDynamicSharedMemorySize, K3_SMEM);
        cudaFuncSetAttribute(k3_conv2_mma,
                             cudaFuncAttributePreferredSharedMemoryCarveout, 100);
        cudaFuncSetAttribute(k5_fc1_mma,
                             cudaFuncAttributeMaxDynamicSharedMemorySize, K5_SMEM);
        cudaFuncSetAttribute(k5_fc1_mma,
                             cudaFuncAttributePreferredSharedMemoryCarveout, 100);
        attr_done = true;
    }

    k0_split_w2<<<288, 256>>>(conv2_w);
    k12_conv1_if_pool<<<2048, 256>>>(x, conv1_w, conv1_b, bn1_g, bn1_b, bn1_m, bn1_v);
    dim3 g3(NTB, 3, 2);
    k3_conv2_mma<<<g3, 256, K3_SMEM>>>(conv2_b, bn2_g, bn2_b, bn2_m, bn2_v);
    k4_if2_pool<<<1152, 256>>>();
    dim3 g5(18, 16);
    k5_fc1_mma<<<g5, 256, K5_SMEM>>>(fc1_w);
    k6_lif1<<<144, 256>>>(fc1_b);
    k7_fc2<<<64, 128>>>(fc2_w, fc2_b);
    k8_lif2<<<16, 256>>>();
    k9_fc3<<<1, 256>>>(fc3_w, fc3_b, (float*)d_out);
}

// round 14
// speedup vs baseline: 1.1083x; 1.0132x over previous
#include <cuda_runtime.h>
#include <cuda_pipeline.h>
#include <cuda_fp16.h>
#include <cstdint>

// SJCSNN spiking CNN forward, T=8, B=32, out [32,7] f32.
// conv2 AND fc1: fp16 mma.m16n8k16, scaled 2-term weight split, single fp32 acc
//   (spikes {0,1} exact in fp16; lo-term A = spikes*2^-11 via bit-mask trick,
//    lo-term B = (w - fp16(w)) * 2^11).
// R13: R11 base (tcgen05 is NOT compilable at this target — compute_103 PTX).
//   k3 A-plane smem stride 260 -> 264: bank = 8*qc + qr, injective over the
//   warp -> A fragment LDS fully conflict-free (was 2-way on 24/32 lanes).

#define NTB 256  // T*B

// ---- scratch (device globals; no allocations) ----
__device__ __align__(16) uint32_t g_p1h[NTB * 64 * 676];   // IF1+pool spikes, fp16 pair-packed, PADDED 26x26
__device__ __align__(16) float g_c2[NTB * 128 * 24 * 24];  // conv2+bn2 output
__device__ __align__(16) uint32_t g_fh[NTB * 9216];        // IF2+pool spikes, fp16 pair-packed flat
__device__ float g_y1p[16 * NTB * 1152];                   // fc1 split-K partials (16)
__device__ __align__(16) float g_l1[NTB * 1152];           // LIF1 spikes
__device__ float g_y2[NTB * 128];                          // fc2 output
__device__ float g_l2[NTB * 128];                          // LIF2 spikes
// conv2 weights fp16 split: [tap(9)][cinpair(64)][cout(128)][hi,lo] as half2 words
__device__ __align__(16) uint32_t g_w2p[9 * 64 * 128 * 2];

// ---------------- mma helper ----------------
__device__ __forceinline__ void mma_f16(float c[4], const uint32_t a[4],
                                        uint32_t b0, uint32_t b1) {
    asm volatile(
        "mma.sync.aligned.m16n8k16.row.col.f32.f16.f16.f32 "
        "{%0,%1,%2,%3}, {%4,%5,%6,%7}, {%8,%9}, {%0,%1,%2,%3};"
        : "+f"(c[0]), "+f"(c[1]), "+f"(c[2]), "+f"(c[3])
        : "r"(a[0]), "r"(a[1]), "r"(a[2]), "r"(a[3]), "r"(b0), "r"(b1));
}

// ---------------- K0: conv2 weight fp16 split, pair-packed ----------------
__global__ __launch_bounds__(256) void k0_split_w2(const float* __restrict__ w2)
{
    int i = blockIdx.x * 256 + threadIdx.x;  // 73728 exact
    int co = i & 127;
    int r = i >> 7;              // tap*64 + p
    int p = r & 63, tap = r >> 6;
    int c0 = 2 * p, c1 = c0 + 1;
    float w0 = w2[co * 1152 + c0 * 9 + tap];
    float w1 = w2[co * 1152 + c1 * 9 + tap];
    __half h0 = __float2half_rn(w0);
    __half h1 = __float2half_rn(w1);
    __half l0 = __float2half_rn((w0 - __half2float(h0)) * 2048.0f);
    __half l1 = __float2half_rn((w1 - __half2float(h1)) * 2048.0f);
    uint32_t whi = (uint32_t)__half_as_ushort(h0) | ((uint32_t)__half_as_ushort(h1) << 16);
    uint32_t wlo = (uint32_t)__half_as_ushort(l0) | ((uint32_t)__half_as_ushort(l1) << 16);
    g_w2p[(r * 128 + co) * 2]     = whi;
    g_w2p[(r * 128 + co) * 2 + 1] = wlo;
}

// ---------------- K12: conv1 (1->128) + BN1 + IF1 + 2x2 maxpool, fused ----------------
// Also zeroes the 26x26 plane borders for its 8 (t) planes (replaces global memset).
__global__ __launch_bounds__(256) void k12_conv1_if_pool(
    const float* __restrict__ x, const float* __restrict__ w,
    const float* __restrict__ cb, const float* __restrict__ bg,
    const float* __restrict__ bb, const float* __restrict__ bm,
    const float* __restrict__ bv)
{
    __shared__ float sx[2500];       // 50x50 padded input
    __shared__ float sh[2][2304];    // h planes for the 2 channels
    int b = blockIdx.x >> 6, pair = blockIdx.x & 63;
    int tid = threadIdx.x;
    for (int i = tid; i < 2500; i += 256) sx[i] = 0.0f;

    // zero plane borders (100 words/plane x 8 t-planes), interior written below
    {
        int pb = pair * 676;
#pragma unroll
        for (int ii = 0; ii < 4; ii++) {
            int i = tid + ii * 256;
            if (i < 800) {
                int t = i / 100;
                int e = i - t * 100;
                int off;
                if (e < 26) off = e;                       // row 0
                else if (e < 52) off = 25 * 26 + (e - 26); // row 25
                else if (e < 76) off = (e - 52 + 1) * 26;  // col 0, rows 1..24
                else off = (e - 76 + 1) * 26 + 25;         // col 25, rows 1..24
                g_p1h[(t * 32 + b) * 64 * 676 + pb + off] = 0u;
            }
        }
    }
    __syncthreads();
    const float* xp = x + b * 2304;
    for (int i = tid; i < 2304; i += 256) {
        int r = i / 48, q = i - r * 48;
        sx[(r + 1) * 50 + q + 1] = xp[i];
    }
    __syncthreads();
#pragma unroll
    for (int half = 0; half < 2; half++) {
        int c = 2 * pair + half;
        float wr[9];
#pragma unroll
        for (int k = 0; k < 9; k++) wr[k] = w[c * 9 + k];
        float sc = bg[c] * rsqrtf(bv[c] + 1e-5f);
        float sf = (cb[c] - bm[c]) * sc + bb[c];
        for (int p = tid; p < 2304; p += 256) {
            int y = p / 48, xx = p - y * 48;
            const float* sp = sx + y * 50 + xx;
            float a = sp[0] * wr[0] + sp[1] * wr[1] + sp[2] * wr[2]
                    + sp[50] * wr[3] + sp[51] * wr[4] + sp[52] * wr[5]
                    + sp[100] * wr[6] + sp[101] * wr[7] + sp[102] * wr[8];
            sh[half][p] = a * sc + sf;
        }
    }
    __syncthreads();
    for (int p = tid; p < 576; p += 256) {
        int oy = p / 24, ox = p - oy * 24;
        int base = (2 * oy) * 48 + 2 * ox;
        float a0 = sh[0][base], a1 = sh[0][base + 1], a2 = sh[0][base + 48], a3 = sh[0][base + 49];
        float c0 = sh[1][base], c1 = sh[1][base + 1], c2 = sh[1][base + 48], c3 = sh[1][base + 49];
        float va0 = 0.f, va1 = 0.f, va2 = 0.f, va3 = 0.f;
        float vc0 = 0.f, vc1 = 0.f, vc2 = 0.f, vc3 = 0.f;
        int pin = pair * 676 + (oy + 1) * 26 + ox + 1;
#pragma unroll
        for (int t = 0; t < 8; t++) {
            va0 += a0; va1 += a1; va2 += a2; va3 += a3;
            vc0 += c0; vc1 += c1; vc2 += c2; vc3 += c3;
            bool sa0 = va0 >= 1.f, sa1 = va1 >= 1.f, sa2 = va2 >= 1.f, sa3 = va3 >= 1.f;
            bool sc0 = vc0 >= 1.f, sc1 = vc1 >= 1.f, sc2 = vc2 >= 1.f, sc3 = vc3 >= 1.f;
            va0 = sa0 ? 0.f : va0; va1 = sa1 ? 0.f : va1;
            va2 = sa2 ? 0.f : va2; va3 = sa3 ? 0.f : va3;
            vc0 = sc0 ? 0.f : vc0; vc1 = sc1 ? 0.f : vc1;
            vc2 = sc2 ? 0.f : vc2; vc3 = sc3 ? 0.f : vc3;
            bool m0 = sa0 | sa1 | sa2 | sa3;
            bool m1 = sc0 | sc1 | sc2 | sc3;
            uint32_t word = (m0 ? 0x3C00u : 0u) | (m1 ? 0x3C000000u : 0u);
            g_p1h[(t * 32 + b) * 64 * 676 + pin] = word;
        }
    }
}

// ---------------- K3: conv2 + BN2, fp16 mma m16n8k16, cp.async double-buffered --------
// 192px M tile, 64-cout N tile, 8 warps 4Mx2N, 2 CTAs/SM.
// A plane stride = 264 words (bank = 8*qc + qr -> conflict-free A LDS).
__global__ __launch_bounds__(256, 2) void k3_conv2_mma(
    const float* __restrict__ cb, const float* __restrict__ bg,
    const float* __restrict__ bb, const float* __restrict__ bm,
    const float* __restrict__ bv)
{
    extern __shared__ uint32_t dyn[];
    uint32_t* sA0 = dyn;                       // 2 x 2112 words (8 pair-planes x 264)
    uint32_t* sB0 = dyn + 4224;                // 2 x 9792 words (72 rows x 136)
    float* sSc = (float*)(dyn + 4224 + 19584); // 64
    float* sSh = sSc + 64;                     // 64

    int n = blockIdx.x;
    int y0g = blockIdx.y;              // 0..2  -> rows y0g*8 .. +7
    int coutbase = blockIdx.z * 64;    // 0 or 64
    int tid = threadIdx.x;
    int lane = tid & 31, warp = tid >> 5;
    int wm = warp & 3, wn = warp >> 2; // 4 x 2 warp grid
    int qr = lane >> 2, qc = lane & 3;

    if (tid < 64) {
        int oc = coutbase + tid;
        float sc = bg[oc] * rsqrtf(bv[oc] + 1e-5f);
        sSc[tid] = sc;
        sSh[tid] = (cb[oc] - bm[oc]) * sc + bb[oc];
    }

    int offr[3], offr8[3];
#pragma unroll
    for (int mf = 0; mf < 3; mf++) {
        int p = wm * 48 + mf * 16 + qr;
        offr[mf] = (p / 24) * 26 + (p % 24);
        int p8 = p + 8;
        offr8[mf] = (p8 / 24) * 26 + (p8 % 24);
    }

    float acc[3][4][4];
#pragma unroll
    for (int mf = 0; mf < 3; mf++)
#pragma unroll
        for (int nf = 0; nf < 4; nf++)
#pragma unroll
            for (int i = 0; i < 4; i++) acc[mf][nf][i] = 0.f;

    int y0 = y0g * 8;
    const uint32_t* pbase = g_p1h + n * 64 * 676 + y0 * 26;

    auto issue = [&](int chunk, int buf) {
        uint32_t* sAb = sA0 + buf * 2112;
        uint32_t* sBb = sB0 + buf * 9792;
        int pb = chunk * 8;  // base cin-pair
        for (int i = tid; i < 520; i += 256) {
            int ci = i / 65, q = i - ci * 65;
            __pipeline_memcpy_async(sAb + ci * 264 + q * 4,
                                    pbase + (pb + ci) * 676 + q * 4, 16);
        }
        // B: 72 rows x 32 cout-pairs, 16B each (2 couts = 4 words)
        for (int i = tid; i < 2304; i += 256) {
            int cp2 = i & 31;
            int r = i >> 5;               // tap*8 + pi
            int pi = r & 7, tap = r >> 3;
            __pipeline_memcpy_async(sBb + r * 136 + cp2 * 4,
                                    g_w2p + ((tap * 64 + pb + pi) * 128 + coutbase + cp2 * 2) * 2,
                                    16);
        }
        __pipeline_commit();
    };

    issue(0, 0);
    for (int c = 0; c < 8; c++) {
        if (c < 7) {
            issue(c + 1, (c + 1) & 1);
            __pipeline_wait_prior(1);
        } else {
            __pipeline_wait_prior(0);
        }
        __syncthreads();
        const uint32_t* sAb = sA0 + (c & 1) * 2112;
        const uint32_t* sBb = sB0 + (c & 1) * 9792;
#pragma unroll
        for (int tap = 0; tap < 9; tap++) {
            int toff = (tap / 3) * 26 + (tap % 3);
            uint32_t ah[3][4], al[3][4];
#pragma unroll
            for (int mf = 0; mf < 3; mf++) {
                ah[mf][0] = sAb[qc * 264 + offr[mf] + toff];
                ah[mf][1] = sAb[qc * 264 + offr8[mf] + toff];
                ah[mf][2] = sAb[(qc + 4) * 264 + offr[mf] + toff];
                ah[mf][3] = sAb[(qc + 4) * 264 + offr8[mf] + toff];
#pragma unroll
                for (int j = 0; j < 4; j++) al[mf][j] = ah[mf][j] & 0x10001000u;
            }
#pragma unroll
            for (int nf = 0; nf < 4; nf++) {
                int ncol = wn * 32 + nf * 8 + qr;
                uint2 b0 = *(const uint2*)(sBb + (tap * 8 + qc) * 136 + ncol * 2);
                uint2 b1 = *(const uint2*)(sBb + (tap * 8 + qc + 4) * 136 + ncol * 2);
#pragma unroll
                for (int mf = 0; mf < 3; mf++) {
                    mma_f16(acc[mf][nf], ah[mf], b0.x, b1.x);
                    mma_f16(acc[mf][nf], al[mf], b0.y, b1.y);
                }
            }
        }
        __syncthreads();
    }

    float* op = g_c2 + (n * 128 + coutbase) * 576 + y0g * 192;
#pragma unroll
    for (int mf = 0; mf < 3; mf++) {
        int p = wm * 48 + mf * 16 + qr;
#pragma unroll
        for (int nf = 0; nf < 4; nf++) {
            int L = wn * 32 + nf * 8 + qc * 2;
            float sc0 = sSc[L], sh0 = sSh[L];
            float sc1 = sSc[L + 1], sh1 = sSh[L + 1];
            op[L * 576 + p]           = acc[mf][nf][0] * sc0 + sh0;
            op[(L + 1) * 576 + p]     = acc[mf][nf][1] * sc1 + sh1;
            op[L * 576 + p + 8]       = acc[mf][nf][2] * sc0 + sh0;
            op[(L + 1) * 576 + p + 8] = acc[mf][nf][3] * sc1 + sh1;
        }
    }
}

// ---------------- K4: IF2 + 2x2 maxpool + flatten, fp16 pair-packed output ----------------
__global__ __launch_bounds__(256) void k4_if2_pool()
{
    int idx = blockIdx.x * 256 + threadIdx.x;  // 294,912 exact
    int oxp = idx % 6;
    int t1 = idx / 6;
    int oy = t1 % 12;
    int t2 = t1 / 12;
    int c = t2 & 127;
    int b = t2 >> 7;
    float va0 = 0.f, va1 = 0.f, va2 = 0.f, va3 = 0.f;
    float vc0 = 0.f, vc1 = 0.f, vc2 = 0.f, vc3 = 0.f;
    int fo = c * 72 + oy * 6 + oxp;
#pragma unroll
    for (int t = 0; t < 8; t++) {
        const float* cp = g_c2 + ((t * 32 + b) * 128 + c) * 576 + (2 * oy) * 24 + 4 * oxp;
        float4 r0 = *(const float4*)cp;
        float4 r1 = *(const float4*)(cp + 24);
        va0 += r0.x; va1 += r0.y; va2 += r1.x; va3 += r1.y;
        vc0 += r0.z; vc1 += r0.w; vc2 += r1.z; vc3 += r1.w;
        bool sa0 = va0 >= 1.f, sa1 = va1 >= 1.f, sa2 = va2 >= 1.f, sa3 = va3 >= 1.f;
        bool sc0 = vc0 >= 1.f, sc1 = vc1 >= 1.f, sc2 = vc2 >= 1.f, sc3 = vc3 >= 1.f;
        va0 = sa0 ? 0.f : va0; va1 = sa1 ? 0.f : va1;
        va2 = sa2 ? 0.f : va2; va3 = sa3 ? 0.f : va3;
        vc0 = sc0 ? 0.f : vc0; vc1 = sc1 ? 0.f : vc1;
        vc2 = sc2 ? 0.f : vc2; vc3 = sc3 ? 0.f : vc3;
        bool m0 = sa0 | sa1 | sa2 | sa3;
        bool m1 = sc0 | sc1 | sc2 | sc3;
        uint32_t word = (m0 ? 0x3C00u : 0u) | (m1 ? 0x3C000000u : 0u);
        g_fh[(t * 32 + b) * 9216 + fo] = word;
    }
}

// ---------------- K5: fc1 GEMM, fp16 mma m16n8k16, split-K=16, cp.async ----------------
__global__ __launch_bounds__(256, 2) void k5_fc1_mma(const float* __restrict__ w1)
{
    extern __shared__ uint32_t dyn5[];
    uint32_t* sA0 = dyn5;                    // 2 x 256*12 words
    float* sB0 = (float*)(dyn5 + 2 * 3072);  // 2 x 64*24 floats

    int n0 = blockIdx.x * 64;
    int z = blockIdx.y;
    int tid = threadIdx.x;
    int lane = tid & 31, warp = tid >> 5;
    int wm = warp & 3, wn = warp >> 2;
    int qr = lane >> 2, qc = lane & 3;

    float acc[4][4][4];
#pragma unroll
    for (int mf = 0; mf < 4; mf++)
#pragma unroll
        for (int nf = 0; nf < 4; nf++)
#pragma unroll
            for (int i = 0; i < 4; i++) acc[mf][nf][i] = 0.f;

    int kbase = z * 1152;

    auto issue = [&](int kc, int buf) {
        int k0 = kbase + kc * 16;
        int kw = k0 >> 1;
        uint32_t* sAb = sA0 + buf * 3072;
        float* sBb = sB0 + buf * 1536;
        for (int v = tid; v < 512; v += 256) {
            int m = v >> 1;
            int hq = (v & 1) * 4;
            __pipeline_memcpy_async(sAb + m * 12 + hq,
                                    g_fh + m * 9216 + kw + hq, 16);
        }
        {
            int nr = tid >> 2;
            int kq = (tid & 3) * 4;
            __pipeline_memcpy_async(sBb + nr * 24 + kq,
                                    w1 + (n0 + nr) * 18432 + k0 + kq, 16);
        }
        __pipeline_commit();
    };

    issue(0, 0);
    for (int kc = 0; kc < 72; kc++) {
        if (kc < 71) {
            issue(kc + 1, (kc + 1) & 1);
            __pipeline_wait_prior(1);
        } else {
            __pipeline_wait_prior(0);
        }
        __syncthreads();
        const uint32_t* sAb = sA0 + (kc & 1) * 3072;
        const float* sBb = sB0 + (kc & 1) * 1536;
        uint32_t ah[4][4], al[4][4];
#pragma unroll
        for (int mf = 0; mf < 4; mf++) {
            int m = wm * 64 + mf * 16 + qr;
            ah[mf][0] = sAb[m * 12 + qc];
            ah[mf][1] = sAb[(m + 8) * 12 + qc];
            ah[mf][2] = sAb[m * 12 + qc + 4];
            ah[mf][3] = sAb[(m + 8) * 12 + qc + 4];
#pragma unroll
            for (int j = 0; j < 4; j++) al[mf][j] = ah[mf][j] & 0x10001000u;
        }
#pragma unroll
        for (int nf = 0; nf < 4; nf++) {
            int nn = wn * 32 + nf * 8 + qr;
            float2 p0 = *(const float2*)(sBb + nn * 24 + 2 * qc);
            float2 p1 = *(const float2*)(sBb + nn * 24 + 2 * qc + 8);
            __half2 h0 = __float22half2_rn(p0);
            __half2 h1 = __float22half2_rn(p1);
            float2 h0f = __half22float2(h0);
            float2 h1f = __half22float2(h1);
            __half2 l0 = __float22half2_rn(
                make_float2((p0.x - h0f.x) * 2048.0f, (p0.y - h0f.y) * 2048.0f));
            __half2 l1 = __float22half2_rn(
                make_float2((p1.x - h1f.x) * 2048.0f, (p1.y - h1f.y) * 2048.0f));
            uint32_t bh0 = *(uint32_t*)&h0, bh1 = *(uint32_t*)&h1;
            uint32_t bl0 = *(uint32_t*)&l0, bl1 = *(uint32_t*)&l1;
#pragma unroll
            for (int mf = 0; mf < 4; mf++) {
                mma_f16(acc[mf][nf], ah[mf], bh0, bh1);
                mma_f16(acc[mf][nf], al[mf], bl0, bl1);
            }
        }
        __syncthreads();
    }

    float* op = g_y1p + z * 294912;
#pragma unroll
    for (int mf = 0; mf < 4; mf++) {
        int m = wm * 64 + mf * 16 + qr;
#pragma unroll
        for (int nf = 0; nf < 4; nf++) {
            int nn = n0 + wn * 32 + nf * 8 + qc * 2;
            op[m * 1152 + nn]           = acc[mf][nf][0];
            op[m * 1152 + nn + 1]       = acc[mf][nf][1];
            op[(m + 8) * 1152 + nn]     = acc[mf][nf][2];
            op[(m + 8) * 1152 + nn + 1] = acc[mf][nf][3];
        }
    }
}

// ---------------- K6: reduce split-K(16) + bias + LIF1 ----------------
__global__ __launch_bounds__(256) void k6_lif1(const float* __restrict__ bias)
{
    int idx = blockIdx.x * 256 + threadIdx.x;  // 36,864 exact
    int o = idx % 1152, b = idx / 1152;
    float bi = bias[o];
    float v = 0.f;
#pragma unroll
    for (int t = 0; t < 8; t++) {
        int row = (t * 32 + b) * 1152 + o;
        float xx = bi;
#pragma unroll
        for (int z = 0; z < 16; z++) xx += g_y1p[z * 294912 + row];
        v += (xx - v) * 0.5f;
        float s = v >= 1.f ? 1.f : 0.f;
        g_l1[row] = s;
        v = v >= 1.f ? 0.f : v;
    }
}

// ---------------- K7: fc2, blocked (4 rows per block, rows in smem) ----------------
__global__ __launch_bounds__(128) void k7_fc2(const float* __restrict__ w,
                                              const float* __restrict__ bias)
{
    __shared__ float srow[4 * 1152];
    int r0 = blockIdx.x * 4;
    int o = threadIdx.x;
    for (int i = o; i < 4608; i += 128) srow[i] = g_l1[r0 * 1152 + i];
    __syncthreads();
    float a0 = 0.f, a1 = 0.f, a2 = 0.f, a3 = 0.f;
    const float4* wp = (const float4*)(w + o * 1152);
#pragma unroll 4
    for (int k = 0; k < 288; k++) {
        float4 wv = wp[k];
        float4 s0 = *(const float4*)&srow[4 * k];
        float4 s1 = *(const float4*)&srow[1152 + 4 * k];
        float4 s2 = *(const float4*)&srow[2304 + 4 * k];
        float4 s3 = *(const float4*)&srow[3456 + 4 * k];
        a0 += s0.x * wv.x + s0.y * wv.y + s0.z * wv.z + s0.w * wv.w;
        a1 += s1.x * wv.x + s1.y * wv.y + s1.z * wv.z + s1.w * wv.w;
        a2 += s2.x * wv.x + s2.y * wv.y + s2.z * wv.z + s2.w * wv.w;
        a3 += s3.x * wv.x + s3.y * wv.y + s3.z * wv.z + s3.w * wv.w;
    }
    float bi = bias[o];
    g_y2[(r0 + 0) * 128 + o] = a0 + bi;
    g_y2[(r0 + 1) * 128 + o] = a1 + bi;
    g_y2[(r0 + 2) * 128 + o] = a2 + bi;
    g_y2[(r0 + 3) * 128 + o] = a3 + bi;
}

// ---------------- K8: LIF2 ----------------
__global__ __launch_bounds__(256) void k8_lif2()
{
    int idx = blockIdx.x * 256 + threadIdx.x;  // 4096 exact
    int o = idx & 127, b = idx >> 7;
    float v = 0.f;
#pragma unroll
    for (int t = 0; t < 8; t++) {
        int row = (t * 32 + b) * 128 + o;
        float xx = g_y2[row];
        v += (xx - v) * 0.5f;
        float s = v >= 1.f ? 1.f : 0.f;
        g_l2[row] = s;
        v = v >= 1.f ? 0.f : v;
    }
}

// ---------------- K9: fc3 + LIF3 + mean over T ----------------
__global__ __launch_bounds__(256) void k9_fc3(const float* __restrict__ w,
                                              const float* __restrict__ bias,
                                              float* __restrict__ out)
{
    int idx = threadIdx.x;
    if (idx >= 224) return;
    int o = idx % 7, b = idx / 7;
    const float4* wp = (const float4*)(w + o * 128);
    float v = 0.f, accm = 0.f;
    float bi = bias[o];
    for (int t = 0; t < 8; t++) {
        const float4* lp = (const float4*)(g_l2 + (t * 32 + b) * 128);
        float y = 0.f;
#pragma unroll
        for (int k = 0; k < 32; k++) {
            float4 a = lp[k], ww = wp[k];
            y += a.x * ww.x + a.y * ww.y + a.z * ww.z + a.w * ww.w;
        }
        y += bi;
        v += (y - v) * 0.5f;
        float s = v >= 1.f ? 1.f : 0.f;
        accm += s;
        v = v >= 1.f ? 0.f : v;
    }
    out[b * 7 + o] = accm * 0.125f;
}

// ---------------- launch ----------------
#define K3_SMEM ((4224 + 19584 + 128) * 4)   // 95744 B
#define K5_SMEM ((2 * 3072 + 2 * 1536) * 4)  // 36864 B

extern "C" void kernel_launch(void* const* d_in, const int* in_sizes, int n_in,
                              void* d_out, int out_size)
{
    const float* x       = (const float*)d_in[0];
    const float* conv1_w = (const float*)d_in[1];
    const float* conv1_b = (const float*)d_in[2];
    const float* bn1_g   = (const float*)d_in[3];
    const float* bn1_b   = (const float*)d_in[4];
    const float* bn1_m   = (const float*)d_in[5];
    const float* bn1_v   = (const float*)d_in[6];
    const float* conv2_w = (const float*)d_in[7];
    const float* conv2_b = (const float*)d_in[8];
    const float* bn2_g   = (const float*)d_in[9];
    const float* bn2_b   = (const float*)d_in[10];
    const float* bn2_m   = (const float*)d_in[11];
    const float* bn2_v   = (const float*)d_in[12];
    const float* fc1_w   = (const float*)d_in[13];
    const float* fc1_b   = (const float*)d_in[14];
    const float* fc2_w   = (const float*)d_in[15];
    const float* fc2_b   = (const float*)d_in[16];
    const float* fc3_w   = (const float*)d_in[17];
    const float* fc3_b   = (const float*)d_in[18];

    static bool attr_done = false;
    if (!attr_done) {
        cudaFuncSetAttribute(k3_conv2_mma,
                             cudaFuncAttributeMaxDynamicSharedMemorySize, K3_SMEM);
        cudaFuncSetAttribute(k3_conv2_mma,
                             cudaFuncAttributePreferredSharedMemoryCarveout, 100);
        cudaFuncSetAttribute(k5_fc1_mma,
                             cudaFuncAttributeMaxDynamicSharedMemorySize, K5_SMEM);
        cudaFuncSetAttribute(k5_fc1_mma,
                             cudaFuncAttributePreferredSharedMemoryCarveout, 100);
        attr_done = true;
    }

    k0_split_w2<<<288, 256>>>(conv2_w);
    k12_conv1_if_pool<<<2048, 256>>>(x, conv1_w, conv1_b, bn1_g, bn1_b, bn1_m, bn1_v);
    dim3 g3(NTB, 3, 2);
    k3_conv2_mma<<<g3, 256, K3_SMEM>>>(conv2_b, bn2_g, bn2_b, bn2_m, bn2_v);
    k4_if2_pool<<<1152, 256>>>();
    dim3 g5(18, 16);
    k5_fc1_mma<<<g5, 256, K5_SMEM>>>(fc1_w);
    k6_lif1<<<144, 256>>>(fc1_b);
    k7_fc2<<<64, 128>>>(fc2_w, fc2_b);
    k8_lif2<<<16, 256>>>();
    k9_fc3<<<1, 256>>>(fc3_w, fc3_b, (float*)d_out);
}